// round 14
// baseline (speedup 1.0000x reference)
#include <cuda_runtime.h>
#include <cuda_fp16.h>
#include <cstdint>
#include <math.h>
#include <float.h>

#define BATCH 4
#define NPILLAR 5000
#define NPT 100
#define CPT 8
#define NX 240
#define NY 240
#define F 64      // PN_FEAT
#define C1 128    // conv hidden channels

// ---------------- scratch (device globals; no allocation allowed) ----------------
__device__ __align__(16) __half g_img[BATCH * NX * NY * F];    // fp16 BEV image
__device__ __align__(16) __half g_x1 [BATCH * NX * NY * C1];   // fp16 conv1 output
__device__ int g_winner[BATCH * NX * NY];
// fp16 weights, K-blocked fragment-order layout [tap][k/8][co][8]
__device__ __align__(16) __half g_wb1[9 * 64 * 128];    // conv1 (CIN=64)
__device__ __align__(16) __half g_wb2[9 * 128 * 128];   // conv2 (CIN=128)

// ---------------- HMMA + ldmatrix (plain sm_75/80 PTX) ---------------------------
__device__ __forceinline__ void mma_f16(float* d, const uint32_t* a, const uint32_t* b) {
    asm volatile(
        "mma.sync.aligned.m16n8k16.row.col.f32.f16.f16.f32 "
        "{%0,%1,%2,%3}, {%4,%5,%6,%7}, {%8,%9}, {%0,%1,%2,%3};"
        : "+f"(d[0]), "+f"(d[1]), "+f"(d[2]), "+f"(d[3])
        : "r"(a[0]), "r"(a[1]), "r"(a[2]), "r"(a[3]), "r"(b[0]), "r"(b[1]));
}
__device__ __forceinline__ void mma_f16_k8(float* d, const uint32_t* a, uint32_t b) {
    asm volatile(
        "mma.sync.aligned.m16n8k8.row.col.f32.f16.f16.f32 "
        "{%0,%1,%2,%3}, {%4,%5}, {%6}, {%0,%1,%2,%3};"
        : "+f"(d[0]), "+f"(d[1]), "+f"(d[2]), "+f"(d[3])
        : "r"(a[0]), "r"(a[1]), "r"(b));
}
__device__ __forceinline__ void ldsm_x4(uint32_t* r, uint32_t addr) {
    asm volatile("ldmatrix.sync.aligned.m8n8.x4.shared.b16 {%0,%1,%2,%3}, [%4];"
        : "=r"(r[0]), "=r"(r[1]), "=r"(r[2]), "=r"(r[3]) : "r"(addr));
}
__device__ __forceinline__ uint32_t smem_u32(const void* p) {
    uint32_t a;
    asm("{ .reg .u64 t; cvta.to.shared.u64 t, %1; cvt.u32.u64 %0, t; }" : "=r"(a) : "l"(p));
    return a;
}
__device__ __forceinline__ void cpasync16(uint32_t s, const void* g) {
    asm volatile("cp.async.cg.shared.global [%0], [%1], 16;" :: "r"(s), "l"(g));
}
#define CP_COMMIT() asm volatile("cp.async.commit_group;" ::: "memory")
#define CP_WAIT(n)  asm volatile("cp.async.wait_group %0;" :: "n"(n) : "memory")
__device__ __forceinline__ float tanh_fast(float x) {
    float y;
    asm("tanh.approx.f32 %0, %1;" : "=f"(y) : "f"(x));
    return y;
}
__device__ __forceinline__ uint32_t pkh2(float a, float b) {
    __half2 h;
    h.x = __float2half_rn(a);
    h.y = __float2half_rn(b);
    return *(uint32_t*)&h;
}

// ---------------- 1) prep: zero BEV image + init winner + conv weight prep -------
__global__ void prep_kernel(const float* __restrict__ cw0, const float* __restrict__ cw1) {
    int tid = blockIdx.x * blockDim.x + threadIdx.x;
    int stride = gridDim.x * blockDim.x;
    const int n8 = BATCH * NX * NY * F / 8;
    uint4 z = make_uint4(0, 0, 0, 0);
    for (int i = tid; i < n8; i += stride)
        reinterpret_cast<uint4*>(g_img)[i] = z;
    for (int i = tid; i < BATCH * NX * NY; i += stride)
        g_winner[i] = -1;
    for (int i = tid; i < 9 * 128 * 64; i += stride) {      // conv1 weights
        int ci = i % 64, co = (i / 64) % 128, tap = i / (64 * 128);
        float v = cw0[((size_t)tap * 64 + ci) * C1 + co];
        g_wb1[((size_t)tap * 8 + (ci >> 3)) * 1024 + co * 8 + (ci & 7)] = __float2half_rn(v);
    }
    for (int i = tid; i < 9 * 128 * 128; i += stride) {     // conv2 weights
        int ci = i % 128, co = (i / 128) % 128, tap = i / (128 * 128);
        float v = cw1[((size_t)tap * 128 + ci) * C1 + co];
        g_wb2[((size_t)tap * 16 + (ci >> 3)) * 1024 + co * 8 + (ci & 7)] = __float2half_rn(v);
    }
}

// ---------------- 2) duplicate-cell winner (last update wins = max pillar idx) ---
__global__ void winner_kernel(const int* __restrict__ idxs) {
    int p = blockIdx.x * blockDim.x + threadIdx.x;
    if (p >= BATCH * NPILLAR) return;
    int b = p / NPILLAR, pl = p % NPILLAR;
    int ix = idxs[2 * p], iy = idxs[2 * p + 1];
    atomicMax(&g_winner[(b * NX + ix) * NY + iy], pl);
}

// ---------------- 3) pointnet, all-HMMA, 8 pillars/CTA, fused scatter ------------
__global__ __launch_bounds__(256) void pointnet_hmma(
    const float* __restrict__ pillars, const int* __restrict__ idxs,
    const float* __restrict__ w0, const float* __restrict__ b0,
    const float* __restrict__ w1, const float* __restrict__ b1) {

    extern __shared__ char sm[];
    __half* sX   = (__half*)sm;                       // 256 * 8  (4096 B)
    __half* sW0h = (__half*)(sm + 4096);              // 64 * 8   (1024 B)  [n][k]
    __half* sW   = (__half*)(sm + 5120);              // 4096     (8192 B)  [kb][n][8]
    float* sB0  = (float*)(sm + 13312);               // 64
    float* sB1  = sB0 + 64;                           // 64
    float* sRed = sB1 + 64;                           // 512
    int*   sCode = (int*)(sRed + 512);                // 256

    int tid = threadIdx.x, lane = tid & 31, wid = tid >> 5;

    if (tid < 64) { sB0[tid] = b0[tid]; sB1[tid] = b1[tid]; }
    for (int i = tid; i < 512; i += 256) {            // w0: [k=8][n=64] -> [n][k]
        int k = i >> 6, n = i & 63;
        sW0h[n * 8 + k] = __float2half_rn(w0[i]);
    }
    for (int i = tid; i < 4096; i += 256) {           // w1 -> K-blocked
        int k = i >> 6, n = i & 63;
        sW[(k >> 3) * 512 + n * 8 + (k & 7)] = __float2half_rn(w1[i]);
    }
    __syncthreads();

    const int gi = lane >> 2, q2 = (lane & 3) * 2;
    const int wbase = wid * 32;

    for (int it = 0; it < 4; ++it) {
        const int pbase = blockIdx.x * 8 + it * 2;

        {   // ---- stage X: one thread per row, fp16 [row][8] ----
            int row = tid;
            int pt = row & 127;
            if (pt < NPT) {
                int pil = pbase + (row >> 7);
                const float4* px = (const float4*)(pillars + ((size_t)pil * NPT + pt) * CPT);
                float4 A = __ldg(px), B = __ldg(px + 1);
                float x[8] = {A.x, A.y, A.z, A.w, B.x, B.y, B.z, B.w};
                float ss = 0.f;
                #pragma unroll
                for (int k = 0; k < 8; k++) ss += x[k] * x[k];
                sCode[row] = (ss < 1e12f) ? 0 : 1;
                uint4 v;
                v.x = pkh2(x[0], x[1]); v.y = pkh2(x[2], x[3]);
                v.z = pkh2(x[4], x[5]); v.w = pkh2(x[6], x[7]);
                *(uint4*)&sX[row * 8] = v;
            } else {
                sCode[row] = 2;
                *(uint4*)&sX[row * 8] = make_uint4(0, 0, 0, 0);
            }
        }
        __syncthreads();

        // ---- layer 0: m16n8k8, acc initialized with bias ----
        float acc0[2][8][4];
        uint32_t ax[2][2];
        #pragma unroll
        for (int mt = 0; mt < 2; mt++) {
            ax[mt][0] = *(const uint32_t*)&sX[(wbase + mt * 16 + gi) * 8 + q2];
            ax[mt][1] = *(const uint32_t*)&sX[(wbase + mt * 16 + 8 + gi) * 8 + q2];
        }
        #pragma unroll
        for (int nt = 0; nt < 8; nt++) {
            float bA = sB0[nt * 8 + q2], bB = sB0[nt * 8 + q2 + 1];
            uint32_t b = *(const uint32_t*)&sW0h[(nt * 8 + gi) * 8 + q2];
            #pragma unroll
            for (int mt = 0; mt < 2; mt++) {
                acc0[mt][nt][0] = bA; acc0[mt][nt][1] = bB;
                acc0[mt][nt][2] = bA; acc0[mt][nt][3] = bB;
                mma_f16_k8(acc0[mt][nt], ax[mt], b);
            }
        }

        // ---- tanh + repack in registers (D-frag == A-frag) ----
        uint32_t aH[2][4][4];
        #pragma unroll
        for (int mt = 0; mt < 2; mt++)
        #pragma unroll
        for (int j = 0; j < 4; j++) {
            aH[mt][j][0] = pkh2(tanh_fast(acc0[mt][2 * j][0]),     tanh_fast(acc0[mt][2 * j][1]));
            aH[mt][j][1] = pkh2(tanh_fast(acc0[mt][2 * j][2]),     tanh_fast(acc0[mt][2 * j][3]));
            aH[mt][j][2] = pkh2(tanh_fast(acc0[mt][2 * j + 1][0]), tanh_fast(acc0[mt][2 * j + 1][1]));
            aH[mt][j][3] = pkh2(tanh_fast(acc0[mt][2 * j + 1][2]), tanh_fast(acc0[mt][2 * j + 1][3]));
        }

        // ---- layer 1: m16n8k16, A from registers ----
        float acc[2][8][4] = {};
        #pragma unroll
        for (int j = 0; j < 4; j++) {
            const __half* wp = &sW[(2 * j) * 512 + q2];
            #pragma unroll
            for (int nt = 0; nt < 8; nt++) {
                const int n = nt * 8 + gi;
                uint32_t b[2];
                b[0] = *(const uint32_t*)&wp[n * 8];
                b[1] = *(const uint32_t*)&wp[n * 8 + 512];
                mma_f16(acc[0][nt], aH[0][j], b);
                mma_f16(acc[1][nt], aH[1][j], b);
            }
        }

        // ---- masked max reduction ----
        #pragma unroll
        for (int nt = 0; nt < 8; nt++) {
            int col = nt * 8 + q2;
            float bA = sB1[col], bB = sB1[col + 1];
            float vA = -FLT_MAX, vB = -FLT_MAX;
            #pragma unroll
            for (int mt = 0; mt < 2; mt++) {
                int r0 = wbase + mt * 16 + gi, r1 = r0 + 8;
                int c0 = sCode[r0], c1 = sCode[r1];
                float f;
                f = (c0 == 0) ? acc[mt][nt][0] + bA : ((c0 == 1) ? 0.f : -FLT_MAX);
                vA = fmaxf(vA, f);
                f = (c1 == 0) ? acc[mt][nt][2] + bA : ((c1 == 1) ? 0.f : -FLT_MAX);
                vA = fmaxf(vA, f);
                f = (c0 == 0) ? acc[mt][nt][1] + bB : ((c0 == 1) ? 0.f : -FLT_MAX);
                vB = fmaxf(vB, f);
                f = (c1 == 0) ? acc[mt][nt][3] + bB : ((c1 == 1) ? 0.f : -FLT_MAX);
                vB = fmaxf(vB, f);
            }
            #pragma unroll
            for (int off = 4; off < 32; off <<= 1) {
                vA = fmaxf(vA, __shfl_xor_sync(0xFFFFFFFFu, vA, off));
                vB = fmaxf(vB, __shfl_xor_sync(0xFFFFFFFFu, vB, off));
            }
            if (gi == 0) {
                sRed[wid * 64 + col]     = vA;
                sRed[wid * 64 + col + 1] = vB;
            }
        }
        __syncthreads();

        // ---- fused scatter: winner-checked direct fp16 write into BEV image ----
        if (tid < 128) {
            int pil = tid >> 6, col = tid & 63;
            const float* r = &sRed[pil * 4 * 64 + col];
            float m = fmaxf(fmaxf(r[0], r[64]), fmaxf(r[128], r[192]));
            int p = pbase + pil;
            int b = p / NPILLAR, pl = p % NPILLAR;
            int ix = __ldg(&idxs[2 * p]), iy = __ldg(&idxs[2 * p + 1]);
            int cell = (b * NX + ix) * NY + iy;
            if (g_winner[cell] == pl)
                g_img[(size_t)cell * F + col] = __float2half_rn(m);
        }
    }
}

// ---------------- 5) 3x3 conv, HMMA fp16, M=256 tile, B direct-LDG ---------------
// CTA: 16x16 px (M=256) x 128 cout. 8 warps = (mwarp 0..3) x (nwarp 0..1).
// Each warp: 4 m-tiles x 8 n-tiles -> 128 acc regs; B fragment LDG amortized
// over 2x more pixels than the M=128 tile. Zero mainloop barriers.
template <int CIN, bool FUSE>
__global__ __launch_bounds__(256, 1) void conv3x3_hmma(
    const __half* __restrict__ in, const __half* __restrict__ wb,
    const float* __restrict__ bias, void* __restrict__ out_,
    const float* __restrict__ w2, const float* __restrict__ b2) {

    constexpr int KP = CIN + 8;             // A stride in halves
    extern __shared__ char smem[];
    __half* sA = (__half*)smem;                                   // 18*18 * KP
    float* sbias = (float*)(smem + 324 * KP * 2);                 // 128
    float* sw2   = sbias + 128;                                   // 128
    float* sRed  = sw2 + 128;                                     // 512

    int tid = threadIdx.x, lane = tid & 31, wid = tid >> 5;
    int bb = blockIdx.z;
    int y0 = blockIdx.y * 16, x0 = blockIdx.x * 16;
    if (tid < 128) {
        sbias[tid] = bias[tid];
        if (FUSE) sw2[tid] = w2[tid];
    }
    uint32_t sA32 = smem_u32(sA);

    // ---- stage halo: 18x18 px x CIN fp16, straight async copy (zero OOB) ----
    constexpr int CH8 = CIN / 8;
    for (int t = tid; t < 324 * CH8; t += 256) {
        int hp = t / CH8, c0 = (t % CH8) * 8;
        int hr = hp / 18, hc = hp % 18;
        int gy = y0 - 1 + hr, gx = x0 - 1 + hc;
        if (gy >= 0 && gy < NX && gx >= 0 && gx < NY)
            cpasync16(sA32 + (hp * KP + c0) * 2,
                      in + (((size_t)bb * NX + gy) * NY + gx) * CIN + c0);
        else
            *(uint4*)&sA[hp * KP + c0] = make_uint4(0, 0, 0, 0);
    }
    CP_COMMIT();
    CP_WAIT(0);
    __syncthreads();                        // the only barrier before the epilogue

    float acc[4][8][4] = {};
    const int mwarp = wid >> 1, nwarp = wid & 1;
    const int gi = lane >> 2;
    const int q2 = (lane & 3) * 2;
    const int le = lane & 7;
    const int lt = lane >> 3;

    // per-thread global B base: fragment word (n*8 + q2) for n = nwarp*64 + gi
    const __half* wB = wb + (nwarp * 64 + gi) * 8 + q2;

    for (int tap = 0; tap < 9; ++tap) {
        const int dy = tap / 3 - 1, dx = tap % 3 - 1;
        // m-tile g = mwarp*4 + mt covers pixel row (y0+g); in-tile row = px col
        uint32_t aBase[4];
        #pragma unroll
        for (int mt = 0; mt < 4; mt++) {
            int hr = mwarp * 4 + mt + 1 + dy;
            int hp = hr * 18 + (1 + dx) + le + (lt & 1) * 8;
            aBase[mt] = sA32 + (hp * KP + (lt >> 1) * 8) * 2;
        }
        const __half* wT = wB + (size_t)tap * CIN * 128;

        #pragma unroll
        for (int k0 = 0; k0 < CIN; k0 += 16) {
            uint32_t a[4][4];
            #pragma unroll
            for (int mt = 0; mt < 4; mt++) ldsm_x4(a[mt], aBase[mt] + k0 * 2);
            const __half* wK = wT + (k0 >> 3) * 1024;
            #pragma unroll
            for (int nt = 0; nt < 8; nt++) {
                uint32_t b[2];
                b[0] = __ldg((const uint32_t*)(wK + nt * 64));
                b[1] = __ldg((const uint32_t*)(wK + nt * 64 + 1024));
                #pragma unroll
                for (int mt = 0; mt < 4; mt++) mma_f16(acc[mt][nt], a[mt], b);
            }
        }
    }

    if (!FUSE) {
        // ---- epilogue: bias + fast tanh -> fp16 store (feeds conv2) ----
        __half* out = (__half*)out_;
        #pragma unroll
        for (int mt = 0; mt < 4; mt++) {
            int gy = y0 + mwarp * 4 + mt;
            #pragma unroll
            for (int half = 0; half < 2; half++) {
                int gx = x0 + gi + half * 8;
                __half* op = &out[(((size_t)bb * NX + gy) * NY + gx) * C1];
                #pragma unroll
                for (int nt = 0; nt < 8; nt++) {
                    int n = nwarp * 64 + nt * 8 + q2;
                    __half2 v;
                    v.x = __float2half_rn(tanh_fast(acc[mt][nt][half * 2 + 0] + sbias[n]));
                    v.y = __float2half_rn(tanh_fast(acc[mt][nt][half * 2 + 1] + sbias[n + 1]));
                    *(__half2*)&op[n] = v;
                }
            }
        }
    } else {
        // ---- fused epilogue: fast tanh + 1x1 conv dot + relu -> fp32 out ----
        float* out = (float*)out_;
        float part[4][2] = {};
        #pragma unroll
        for (int mt = 0; mt < 4; mt++)
        #pragma unroll
        for (int half = 0; half < 2; half++)
        #pragma unroll
        for (int nt = 0; nt < 8; nt++) {
            int n = nwarp * 64 + nt * 8 + q2;
            part[mt][half] += tanh_fast(acc[mt][nt][half * 2 + 0] + sbias[n])     * sw2[n]
                            + tanh_fast(acc[mt][nt][half * 2 + 1] + sbias[n + 1]) * sw2[n + 1];
        }
        #pragma unroll
        for (int mt = 0; mt < 4; mt++)
        #pragma unroll
        for (int half = 0; half < 2; half++) {
            float v = part[mt][half];
            v += __shfl_xor_sync(0xFFFFFFFFu, v, 1);
            v += __shfl_xor_sync(0xFFFFFFFFu, v, 2);
            if ((lane & 3) == 0) {
                int px = (mwarp * 4 + mt) * 16 + gi + half * 8;
                sRed[px * 2 + nwarp] = v;
            }
        }
        __syncthreads();
        {
            float v = sRed[tid * 2] + sRed[tid * 2 + 1] + __ldg(b2);
            int gy = y0 + (tid >> 4), gx = x0 + (tid & 15);
            out[((size_t)bb * NX + gy) * NY + gx] = fmaxf(v, 0.f);
        }
    }
}

// ---------------- host launcher ----------------
extern "C" void kernel_launch(void* const* d_in, const int* in_sizes, int n_in,
                              void* d_out, int out_size) {
    const float* pillars = (const float*)d_in[0];
    const int*   idxs    = (const int*)d_in[1];
    const float* pn_w0 = (const float*)d_in[4];
    const float* pn_b0 = (const float*)d_in[5];
    const float* pn_w1 = (const float*)d_in[6];
    const float* pn_b1 = (const float*)d_in[7];
    const float* cw0   = (const float*)d_in[8];
    const float* cb0   = (const float*)d_in[9];
    const float* cw1   = (const float*)d_in[10];
    const float* cb1   = (const float*)d_in[11];
    const float* cw2   = (const float*)d_in[12];
    const float* cb2   = (const float*)d_in[13];
    float* out = (float*)d_out;

    __half *p_img, *p_x1, *p_wb1, *p_wb2;
    cudaGetSymbolAddress((void**)&p_img, g_img);
    cudaGetSymbolAddress((void**)&p_x1, g_x1);
    cudaGetSymbolAddress((void**)&p_wb1, g_wb1);
    cudaGetSymbolAddress((void**)&p_wb2, g_wb2);

    const int smem1 = 324 * (64 + 8)  * 2 + 768 * 4;   // 49,728 B
    const int smem2 = 324 * (128 + 8) * 2 + 768 * 4;   // 91,200 B
    const int smemP = 13312 + (64 + 64 + 512) * 4 + 256 * 4;
    cudaFuncSetAttribute((const void*)conv3x3_hmma<64, false>,
                         cudaFuncAttributeMaxDynamicSharedMemorySize, smem1);
    cudaFuncSetAttribute((const void*)conv3x3_hmma<128, true>,
                         cudaFuncAttributeMaxDynamicSharedMemorySize, smem2);

    prep_kernel<<<1024, 256>>>(cw0, cw1);
    winner_kernel<<<(BATCH * NPILLAR + 255) / 256, 256>>>(idxs);
    pointnet_hmma<<<BATCH * NPILLAR / 8, 256, smemP>>>(pillars, idxs,
                                                       pn_w0, pn_b0, pn_w1, pn_b1);

    dim3 cgrid(NY / 16, NX / 16, BATCH);   // (15, 15, 4)
    conv3x3_hmma<64, false><<<cgrid, 256, smem1>>>(p_img, p_wb1, cb0, p_x1, nullptr, nullptr);
    conv3x3_hmma<128, true><<<cgrid, 256, smem2>>>(p_x1,  p_wb2, cb1, out,  cw2,     cb2);
}

// round 16
// speedup vs baseline: 1.0649x; 1.0649x over previous
#include <cuda_runtime.h>
#include <cuda_fp16.h>
#include <cstdint>
#include <math.h>
#include <float.h>

#define BATCH 4
#define NPILLAR 5000
#define NPT 100
#define CPT 8
#define NX 240
#define NY 240
#define F 64      // PN_FEAT
#define C1 128    // conv hidden channels

// ---------------- scratch (device globals; no allocation allowed) ----------------
__device__ __align__(16) __half g_img[BATCH * NX * NY * F];    // fp16 BEV image
__device__ __align__(16) __half g_x1 [BATCH * NX * NY * C1];   // fp16 conv1 output
__device__ int g_winner[BATCH * NX * NY];
// fp16 weights, thread-major 16B records:
// addr = (((tap*(CIN/16)+kb16)*2 + nwarp)*4 + ntp)*256 + lane*8 + w*2 + h
// w: (nt=2ntp+ [w>>1], k-block j=[w&1]);  h: half within word
__device__ __align__(16) __half g_wb1[9 * 64 * 128];    // conv1 (CIN=64)
__device__ __align__(16) __half g_wb2[9 * 128 * 128];   // conv2 (CIN=128)

// ---------------- HMMA + ldmatrix (plain sm_75/80 PTX) ---------------------------
__device__ __forceinline__ void mma_f16(float* d, const uint32_t* a, const uint32_t* b) {
    asm volatile(
        "mma.sync.aligned.m16n8k16.row.col.f32.f16.f16.f32 "
        "{%0,%1,%2,%3}, {%4,%5,%6,%7}, {%8,%9}, {%0,%1,%2,%3};"
        : "+f"(d[0]), "+f"(d[1]), "+f"(d[2]), "+f"(d[3])
        : "r"(a[0]), "r"(a[1]), "r"(a[2]), "r"(a[3]), "r"(b[0]), "r"(b[1]));
}
__device__ __forceinline__ void mma_f16_k8(float* d, const uint32_t* a, uint32_t b) {
    asm volatile(
        "mma.sync.aligned.m16n8k8.row.col.f32.f16.f16.f32 "
        "{%0,%1,%2,%3}, {%4,%5}, {%6}, {%0,%1,%2,%3};"
        : "+f"(d[0]), "+f"(d[1]), "+f"(d[2]), "+f"(d[3])
        : "r"(a[0]), "r"(a[1]), "r"(b));
}
__device__ __forceinline__ void ldsm_x4(uint32_t* r, uint32_t addr) {
    asm volatile("ldmatrix.sync.aligned.m8n8.x4.shared.b16 {%0,%1,%2,%3}, [%4];"
        : "=r"(r[0]), "=r"(r[1]), "=r"(r[2]), "=r"(r[3]) : "r"(addr));
}
__device__ __forceinline__ uint32_t smem_u32(const void* p) {
    uint32_t a;
    asm("{ .reg .u64 t; cvta.to.shared.u64 t, %1; cvt.u32.u64 %0, t; }" : "=r"(a) : "l"(p));
    return a;
}
__device__ __forceinline__ void cpasync16(uint32_t s, const void* g) {
    asm volatile("cp.async.cg.shared.global [%0], [%1], 16;" :: "r"(s), "l"(g));
}
#define CP_COMMIT() asm volatile("cp.async.commit_group;" ::: "memory")
#define CP_WAIT(n)  asm volatile("cp.async.wait_group %0;" :: "n"(n) : "memory")
__device__ __forceinline__ float tanh_fast(float x) {
    float y;
    asm("tanh.approx.f32 %0, %1;" : "=f"(y) : "f"(x));
    return y;
}
__device__ __forceinline__ uint32_t pkh2(float a, float b) {
    __half2 h;
    h.x = __float2half_rn(a);
    h.y = __float2half_rn(b);
    return *(uint32_t*)&h;
}

// ---------------- 1) prep: zero BEV image + init winner + conv weight prep -------
template <int CIN>
__device__ __forceinline__ void wprep_one(const float* w, __half* wb, int i) {
    int ci = i % CIN;
    int co = (i / CIN) % 128;
    int tap = i / (CIN * 128);
    float v = w[((size_t)tap * CIN + ci) * C1 + co];
    int kb = ci >> 3, j = kb & 1, kb16 = kb >> 1;
    int qi = (ci & 7) >> 1, h = ci & 1;
    int nwarp = co >> 6, r = co & 63, nt = r >> 3, gi = r & 7;
    int ntp = nt >> 1, w4 = (nt & 1) * 2 + j;
    int lane = gi * 4 + qi;
    int rec = ((tap * (CIN / 16) + kb16) * 2 + nwarp) * 4 + ntp;
    wb[(size_t)rec * 256 + lane * 8 + w4 * 2 + h] = __float2half_rn(v);
}
__global__ void prep_kernel(const float* __restrict__ cw0, const float* __restrict__ cw1) {
    int tid = blockIdx.x * blockDim.x + threadIdx.x;
    int stride = gridDim.x * blockDim.x;
    const int n8 = BATCH * NX * NY * F / 8;
    uint4 z = make_uint4(0, 0, 0, 0);
    for (int i = tid; i < n8; i += stride)
        reinterpret_cast<uint4*>(g_img)[i] = z;
    for (int i = tid; i < BATCH * NX * NY; i += stride)
        g_winner[i] = -1;
    for (int i = tid; i < 9 * 128 * 64; i += stride)  wprep_one<64>(cw0, g_wb1, i);
    for (int i = tid; i < 9 * 128 * 128; i += stride) wprep_one<128>(cw1, g_wb2, i);
}

// ---------------- 2) duplicate-cell winner (last update wins = max pillar idx) ---
__global__ void winner_kernel(const int* __restrict__ idxs) {
    int p = blockIdx.x * blockDim.x + threadIdx.x;
    if (p >= BATCH * NPILLAR) return;
    int b = p / NPILLAR, pl = p % NPILLAR;
    int ix = idxs[2 * p], iy = idxs[2 * p + 1];
    atomicMax(&g_winner[(b * NX + ix) * NY + iy], pl);
}

// ---------------- 3) pointnet, all-HMMA, 8 pillars/CTA, fused scatter ------------
__global__ __launch_bounds__(256) void pointnet_hmma(
    const float* __restrict__ pillars, const int* __restrict__ idxs,
    const float* __restrict__ w0, const float* __restrict__ b0,
    const float* __restrict__ w1, const float* __restrict__ b1) {

    extern __shared__ char sm[];
    __half* sX   = (__half*)sm;                       // 256 * 8  (4096 B)
    __half* sW0h = (__half*)(sm + 4096);              // 64 * 8   (1024 B)  [n][k]
    __half* sW   = (__half*)(sm + 5120);              // 4096     (8192 B)  [kb][n][8]
    float* sB0  = (float*)(sm + 13312);               // 64
    float* sB1  = sB0 + 64;                           // 64
    float* sRed = sB1 + 64;                           // 512
    int*   sCode = (int*)(sRed + 512);                // 256

    int tid = threadIdx.x, lane = tid & 31, wid = tid >> 5;

    if (tid < 64) { sB0[tid] = b0[tid]; sB1[tid] = b1[tid]; }
    for (int i = tid; i < 512; i += 256) {            // w0: [k=8][n=64] -> [n][k]
        int k = i >> 6, n = i & 63;
        sW0h[n * 8 + k] = __float2half_rn(w0[i]);
    }
    for (int i = tid; i < 4096; i += 256) {           // w1 -> K-blocked
        int k = i >> 6, n = i & 63;
        sW[(k >> 3) * 512 + n * 8 + (k & 7)] = __float2half_rn(w1[i]);
    }
    __syncthreads();

    const int gi = lane >> 2, q2 = (lane & 3) * 2;
    const int wbase = wid * 32;

    for (int it = 0; it < 4; ++it) {
        const int pbase = blockIdx.x * 8 + it * 2;

        {   // ---- stage X: one thread per row, fp16 [row][8] ----
            int row = tid;
            int pt = row & 127;
            if (pt < NPT) {
                int pil = pbase + (row >> 7);
                const float4* px = (const float4*)(pillars + ((size_t)pil * NPT + pt) * CPT);
                float4 A = __ldg(px), B = __ldg(px + 1);
                float x[8] = {A.x, A.y, A.z, A.w, B.x, B.y, B.z, B.w};
                float ss = 0.f;
                #pragma unroll
                for (int k = 0; k < 8; k++) ss += x[k] * x[k];
                sCode[row] = (ss < 1e12f) ? 0 : 1;
                uint4 v;
                v.x = pkh2(x[0], x[1]); v.y = pkh2(x[2], x[3]);
                v.z = pkh2(x[4], x[5]); v.w = pkh2(x[6], x[7]);
                *(uint4*)&sX[row * 8] = v;
            } else {
                sCode[row] = 2;
                *(uint4*)&sX[row * 8] = make_uint4(0, 0, 0, 0);
            }
        }
        __syncthreads();

        // ---- layer 0: m16n8k8, acc initialized with bias ----
        float acc0[2][8][4];
        uint32_t ax[2][2];
        #pragma unroll
        for (int mt = 0; mt < 2; mt++) {
            ax[mt][0] = *(const uint32_t*)&sX[(wbase + mt * 16 + gi) * 8 + q2];
            ax[mt][1] = *(const uint32_t*)&sX[(wbase + mt * 16 + 8 + gi) * 8 + q2];
        }
        #pragma unroll
        for (int nt = 0; nt < 8; nt++) {
            float bA = sB0[nt * 8 + q2], bB = sB0[nt * 8 + q2 + 1];
            uint32_t b = *(const uint32_t*)&sW0h[(nt * 8 + gi) * 8 + q2];
            #pragma unroll
            for (int mt = 0; mt < 2; mt++) {
                acc0[mt][nt][0] = bA; acc0[mt][nt][1] = bB;
                acc0[mt][nt][2] = bA; acc0[mt][nt][3] = bB;
                mma_f16_k8(acc0[mt][nt], ax[mt], b);
            }
        }

        // ---- tanh + repack in registers (D-frag == A-frag) ----
        uint32_t aH[2][4][4];
        #pragma unroll
        for (int mt = 0; mt < 2; mt++)
        #pragma unroll
        for (int j = 0; j < 4; j++) {
            aH[mt][j][0] = pkh2(tanh_fast(acc0[mt][2 * j][0]),     tanh_fast(acc0[mt][2 * j][1]));
            aH[mt][j][1] = pkh2(tanh_fast(acc0[mt][2 * j][2]),     tanh_fast(acc0[mt][2 * j][3]));
            aH[mt][j][2] = pkh2(tanh_fast(acc0[mt][2 * j + 1][0]), tanh_fast(acc0[mt][2 * j + 1][1]));
            aH[mt][j][3] = pkh2(tanh_fast(acc0[mt][2 * j + 1][2]), tanh_fast(acc0[mt][2 * j + 1][3]));
        }

        // ---- layer 1: m16n8k16, A from registers ----
        float acc[2][8][4] = {};
        #pragma unroll
        for (int j = 0; j < 4; j++) {
            const __half* wp = &sW[(2 * j) * 512 + q2];
            #pragma unroll
            for (int nt = 0; nt < 8; nt++) {
                const int n = nt * 8 + gi;
                uint32_t b[2];
                b[0] = *(const uint32_t*)&wp[n * 8];
                b[1] = *(const uint32_t*)&wp[n * 8 + 512];
                mma_f16(acc[0][nt], aH[0][j], b);
                mma_f16(acc[1][nt], aH[1][j], b);
            }
        }

        // ---- masked max reduction ----
        #pragma unroll
        for (int nt = 0; nt < 8; nt++) {
            int col = nt * 8 + q2;
            float bA = sB1[col], bB = sB1[col + 1];
            float vA = -FLT_MAX, vB = -FLT_MAX;
            #pragma unroll
            for (int mt = 0; mt < 2; mt++) {
                int r0 = wbase + mt * 16 + gi, r1 = r0 + 8;
                int c0 = sCode[r0], c1 = sCode[r1];
                float f;
                f = (c0 == 0) ? acc[mt][nt][0] + bA : ((c0 == 1) ? 0.f : -FLT_MAX);
                vA = fmaxf(vA, f);
                f = (c1 == 0) ? acc[mt][nt][2] + bA : ((c1 == 1) ? 0.f : -FLT_MAX);
                vA = fmaxf(vA, f);
                f = (c0 == 0) ? acc[mt][nt][1] + bB : ((c0 == 1) ? 0.f : -FLT_MAX);
                vB = fmaxf(vB, f);
                f = (c1 == 0) ? acc[mt][nt][3] + bB : ((c1 == 1) ? 0.f : -FLT_MAX);
                vB = fmaxf(vB, f);
            }
            #pragma unroll
            for (int off = 4; off < 32; off <<= 1) {
                vA = fmaxf(vA, __shfl_xor_sync(0xFFFFFFFFu, vA, off));
                vB = fmaxf(vB, __shfl_xor_sync(0xFFFFFFFFu, vB, off));
            }
            if (gi == 0) {
                sRed[wid * 64 + col]     = vA;
                sRed[wid * 64 + col + 1] = vB;
            }
        }
        __syncthreads();

        // ---- fused scatter: winner-checked direct fp16 write into BEV image ----
        if (tid < 128) {
            int pil = tid >> 6, col = tid & 63;
            const float* r = &sRed[pil * 4 * 64 + col];
            float m = fmaxf(fmaxf(r[0], r[64]), fmaxf(r[128], r[192]));
            int p = pbase + pil;
            int b = p / NPILLAR, pl = p % NPILLAR;
            int ix = __ldg(&idxs[2 * p]), iy = __ldg(&idxs[2 * p + 1]);
            int cell = (b * NX + ix) * NY + iy;
            if (g_winner[cell] == pl)
                g_img[(size_t)cell * F + col] = __float2half_rn(m);
        }
    }
}

// ---------------- 5) 3x3 conv, HMMA fp16, M=128 tile, LDG.128 B records ----------
// CTA: 8x16 px (M=128) x 128 cout. 8 warps = (mwarp 0..3) x (nwarp 0..1).
// Per kstep: 2 LDSM + 4 LDG.128 + 16 HMMA (73% HMMA mix). Zero mainloop barriers.
template <int CIN, bool FUSE>
__global__ __launch_bounds__(256, 2) void conv3x3_hmma(
    const __half* __restrict__ in, const __half* __restrict__ wb,
    const float* __restrict__ bias, void* __restrict__ out_,
    const float* __restrict__ w2, const float* __restrict__ b2) {

    constexpr int KP = CIN + 8;             // A stride in halves
    extern __shared__ char smem[];
    __half* sA = (__half*)smem;                                   // 180 * KP
    float* sbias = (float*)(smem + 180 * KP * 2);                 // 128
    float* sw2   = sbias + 128;                                   // 128
    float* sRed  = sw2 + 128;                                     // 256

    int tid = threadIdx.x, lane = tid & 31, wid = tid >> 5;
    int bb = blockIdx.z;
    int y0 = blockIdx.y * 8, x0 = blockIdx.x * 16;
    if (tid < 128) {
        sbias[tid] = bias[tid];
        if (FUSE) sw2[tid] = w2[tid];
    }
    uint32_t sA32 = smem_u32(sA);

    // ---- stage halo: 180 px x CIN fp16, straight async copy (zero OOB) ----
    constexpr int CH8 = CIN / 8;
    for (int t = tid; t < 180 * CH8; t += 256) {
        int hp = t / CH8, c0 = (t % CH8) * 8;
        int hr = hp / 18, hc = hp % 18;
        int gy = y0 - 1 + hr, gx = x0 - 1 + hc;
        if (gy >= 0 && gy < NX && gx >= 0 && gx < NY)
            cpasync16(sA32 + (hp * KP + c0) * 2,
                      in + (((size_t)bb * NX + gy) * NY + gx) * CIN + c0);
        else
            *(uint4*)&sA[hp * KP + c0] = make_uint4(0, 0, 0, 0);
    }
    CP_COMMIT();
    CP_WAIT(0);
    __syncthreads();                        // the only barrier before the epilogue

    float acc[2][8][4] = {};
    const int mwarp = wid >> 1, nwarp = wid & 1;
    const int gi = lane >> 2;
    const int q2 = (lane & 3) * 2;
    const int le = lane & 7;
    const int lt = lane >> 3;

    // per-thread B record base: [tap][kb16][nwarp][ntp][lane] 16B records
    const __half* wB = wb + (nwarp * 4) * 256 + lane * 8;

    for (int tap = 0; tap < 9; ++tap) {
        const int dy = tap / 3 - 1, dx = tap % 3 - 1;
        uint32_t aBase[2];
        #pragma unroll
        for (int mt = 0; mt < 2; mt++) {
            int hr = mwarp * 2 + mt + 1 + dy;
            int pxrow = hr * 18 + (1 + dx) + le + (lt & 1) * 8;
            aBase[mt] = sA32 + (pxrow * KP + (lt >> 1) * 8) * 2;
        }
        const __half* wT = wB + (size_t)tap * CIN * 128;

        #pragma unroll
        for (int k0 = 0; k0 < CIN; k0 += 16) {
            uint32_t a[2][4];
            ldsm_x4(a[0], aBase[0] + k0 * 2);
            ldsm_x4(a[1], aBase[1] + k0 * 2);
            const __half* wK = wT + (k0 >> 4) * 2048;
            #pragma unroll
            for (int ntp = 0; ntp < 4; ntp++) {
                uint4 bv = __ldg((const uint4*)(wK + ntp * 256));
                uint32_t b01[2] = {bv.x, bv.y};
                uint32_t b23[2] = {bv.z, bv.w};
                mma_f16(acc[0][2 * ntp],     a[0], b01);
                mma_f16(acc[1][2 * ntp],     a[1], b01);
                mma_f16(acc[0][2 * ntp + 1], a[0], b23);
                mma_f16(acc[1][2 * ntp + 1], a[1], b23);
            }
        }
    }

    if (!FUSE) {
        // ---- epilogue: bias + fast tanh -> fp16 store (feeds conv2) ----
        __half* out = (__half*)out_;
        #pragma unroll
        for (int mt = 0; mt < 2; mt++) {
            int gy = y0 + mwarp * 2 + mt;
            #pragma unroll
            for (int half = 0; half < 2; half++) {
                int gx = x0 + gi + half * 8;
                __half* op = &out[(((size_t)bb * NX + gy) * NY + gx) * C1];
                #pragma unroll
                for (int nt = 0; nt < 8; nt++) {
                    int n = nwarp * 64 + nt * 8 + q2;
                    __half2 v;
                    v.x = __float2half_rn(tanh_fast(acc[mt][nt][half * 2 + 0] + sbias[n]));
                    v.y = __float2half_rn(tanh_fast(acc[mt][nt][half * 2 + 1] + sbias[n + 1]));
                    *(__half2*)&op[n] = v;
                }
            }
        }
    } else {
        // ---- fused epilogue: fast tanh + 1x1 conv dot + relu -> fp32 out ----
        float* out = (float*)out_;
        float part[2][2] = {};
        #pragma unroll
        for (int mt = 0; mt < 2; mt++)
        #pragma unroll
        for (int half = 0; half < 2; half++)
        #pragma unroll
        for (int nt = 0; nt < 8; nt++) {
            int n = nwarp * 64 + nt * 8 + q2;
            part[mt][half] += tanh_fast(acc[mt][nt][half * 2 + 0] + sbias[n])     * sw2[n]
                            + tanh_fast(acc[mt][nt][half * 2 + 1] + sbias[n + 1]) * sw2[n + 1];
        }
        #pragma unroll
        for (int mt = 0; mt < 2; mt++)
        #pragma unroll
        for (int half = 0; half < 2; half++) {
            float v = part[mt][half];
            v += __shfl_xor_sync(0xFFFFFFFFu, v, 1);
            v += __shfl_xor_sync(0xFFFFFFFFu, v, 2);
            if ((lane & 3) == 0) {
                int px = (mwarp * 2 + mt) * 16 + gi + half * 8;
                sRed[px * 2 + nwarp] = v;
            }
        }
        __syncthreads();
        if (tid < 128) {
            float v = sRed[tid * 2] + sRed[tid * 2 + 1] + __ldg(b2);
            int gy = y0 + (tid >> 4), gx = x0 + (tid & 15);
            out[((size_t)bb * NX + gy) * NY + gx] = fmaxf(v, 0.f);
        }
    }
}

// ---------------- host launcher ----------------
extern "C" void kernel_launch(void* const* d_in, const int* in_sizes, int n_in,
                              void* d_out, int out_size) {
    const float* pillars = (const float*)d_in[0];
    const int*   idxs    = (const int*)d_in[1];
    const float* pn_w0 = (const float*)d_in[4];
    const float* pn_b0 = (const float*)d_in[5];
    const float* pn_w1 = (const float*)d_in[6];
    const float* pn_b1 = (const float*)d_in[7];
    const float* cw0   = (const float*)d_in[8];
    const float* cb0   = (const float*)d_in[9];
    const float* cw1   = (const float*)d_in[10];
    const float* cb1   = (const float*)d_in[11];
    const float* cw2   = (const float*)d_in[12];
    const float* cb2   = (const float*)d_in[13];
    float* out = (float*)d_out;

    __half *p_img, *p_x1, *p_wb1, *p_wb2;
    cudaGetSymbolAddress((void**)&p_img, g_img);
    cudaGetSymbolAddress((void**)&p_x1, g_x1);
    cudaGetSymbolAddress((void**)&p_wb1, g_wb1);
    cudaGetSymbolAddress((void**)&p_wb2, g_wb2);

    const int smem1 = 180 * (64 + 8)  * 2 + 512 * 4;   // 27,968 B
    const int smem2 = 180 * (128 + 8) * 2 + 512 * 4;   // 51,008 B
    const int smemP = 13312 + (64 + 64 + 512) * 4 + 256 * 4;
    cudaFuncSetAttribute((const void*)conv3x3_hmma<64, false>,
                         cudaFuncAttributeMaxDynamicSharedMemorySize, smem1);
    cudaFuncSetAttribute((const void*)conv3x3_hmma<128, true>,
                         cudaFuncAttributeMaxDynamicSharedMemorySize, smem2);

    prep_kernel<<<1024, 256>>>(cw0, cw1);
    winner_kernel<<<(BATCH * NPILLAR + 255) / 256, 256>>>(idxs);
    pointnet_hmma<<<BATCH * NPILLAR / 8, 256, smemP>>>(pillars, idxs,
                                                       pn_w0, pn_b0, pn_w1, pn_b1);

    dim3 cgrid(NX / 16, NY / 8, BATCH);   // (15, 30, 4)
    conv3x3_hmma<64, false><<<cgrid, 256, smem1>>>(p_img, p_wb1, cb0, p_x1, nullptr, nullptr);
    conv3x3_hmma<128, true><<<cgrid, 256, smem2>>>(p_x1,  p_wb2, cb1, out,  cw2,     cb2);
}